// round 8
// baseline (speedup 1.0000x reference)
#include <cuda_runtime.h>

// DegreePrediction: y[u] = sum_{s,t,v} (x*W_t)[s,t] * (W_r*r_zeros + r_const)[s,t,u,v]
// N = 80. Three 80^4 fp32 tensors (491.5 MB) streamed once.
//
// R8: R7's discovery — the old 5.5 TB/s "ceiling" was the conflicting
// shared-atomic epilogue throttling the L1tex/LDG-return path. With the cheap
// epilogue (STS transpose + 80-thread gather + one acq_rel counter), go back
// to the plain 32-reg mainloop for 6 blocks/SM (60 warps, ~93% occ) and halve
// block granularity (K_SLICES=2, 3200 blocks -> 3.6 waves) to shrink the
// partial-wave tail.
//
// Layout: slice (s,t) = 1600 contiguous float4; u-row = 20 float4; thread tid,
// iter j reads float4 tid+320*j -> u = tid/20 + 16*j (constant per thread,j).

#define NN 80
#define SLICE_FLOATS (NN * NN)      // 6400
#define THREADS 320
#define J_ITERS 5
#define K_SLICES 2
#define NUM_BLOCKS ((NN * NN) / K_SLICES)   // 3200

__device__ float    g_scratch[NN];   // zero at load; kernel keeps it net-zero
__device__ unsigned g_count;         // ditto

__device__ __forceinline__ unsigned atom_inc_acq_rel(unsigned* p) {
    unsigned old;
    asm volatile("atom.add.acq_rel.gpu.global.u32 %0, [%1], 1;"
                 : "=r"(old) : "l"(p) : "memory");
    return old;
}

__global__ __launch_bounds__(THREADS, 6)
void degree_pred_kernel(const float* __restrict__ x,
                        const float* __restrict__ r_zeros,
                        const float* __restrict__ r_const,
                        const float* __restrict__ weights_t,
                        const float* __restrict__ weights_r,
                        float* __restrict__ out)
{
    __shared__ float y_part[J_ITERS][THREADS];
    __shared__ bool is_last;
    const int tid = threadIdx.x;

    const int st0 = blockIdx.x * K_SLICES;

    float a[K_SLICES];
#pragma unroll
    for (int k = 0; k < K_SLICES; k++)
        a[k] = __ldg(&x[st0 + k]) * __ldg(&weights_t[st0 + k]);

    float acc[J_ITERS];
#pragma unroll
    for (int j = 0; j < J_ITERS; j++) acc[j] = 0.0f;

#pragma unroll
    for (int k = 0; k < K_SLICES; k++) {
        const size_t base = (size_t)(st0 + k) * SLICE_FLOATS;
        const float4* __restrict__ rz = reinterpret_cast<const float4*>(r_zeros   + base);
        const float4* __restrict__ rc = reinterpret_cast<const float4*>(r_const   + base);
        const float4* __restrict__ wr = reinterpret_cast<const float4*>(weights_r + base);

#pragma unroll
        for (int j = 0; j < J_ITERS; j++) {
            const int p = tid + THREADS * j;
            const float4 z = __ldcs(&rz[p]);
            const float4 c = __ldcs(&rc[p]);
            const float4 w = __ldcs(&wr[p]);
            float t = (c.x + c.y) + (c.z + c.w);
            t = fmaf(w.x, z.x, t);
            t = fmaf(w.y, z.y, t);
            t = fmaf(w.z, z.z, t);
            t = fmaf(w.w, z.w, t);
            acc[j] = fmaf(a[k], t, acc[j]);
        }
    }

    // ---- epilogue: conflict-free STS transpose + 80-thread gather ----
#pragma unroll
    for (int j = 0; j < J_ITERS; j++)
        y_part[j][tid] = acc[j];
    __syncthreads();

    if (tid < NN) {
        const int u = tid;
        const int j = u >> 4;            // u / 16
        const int b = (u & 15) * 20;     // first of 20 contributing threads
        float s = 0.0f;
#pragma unroll
        for (int d = 0; d < 20; d++)
            s += y_part[j][b + d];
        atomicAdd(&g_scratch[u], s);     // relaxed; published by acq_rel below
    }
    __syncthreads();

    // ---- last-block finalize (no full membar, no L1 flush) ----
    if (tid == 0)
        is_last = (atom_inc_acq_rel(&g_count) == (unsigned)(NUM_BLOCKS - 1));
    __syncthreads();

    if (is_last) {
        if (tid < NN) {
            float v = __ldcg(&g_scratch[tid]);   // L2 read, coherent w/ atomics
            out[tid] = v;
            g_scratch[tid] = 0.0f;               // restore initial state
        }
        __syncthreads();
        if (tid == 0) g_count = 0u;              // restore initial state
    }
}

extern "C" void kernel_launch(void* const* d_in, const int* in_sizes, int n_in,
                              void* d_out, int out_size)
{
    const float* x         = (const float*)d_in[0];
    const float* r_zeros   = (const float*)d_in[1];
    const float* r_const   = (const float*)d_in[2];
    const float* weights_t = (const float*)d_in[3];
    const float* weights_r = (const float*)d_in[4];
    float* out = (float*)d_out;

    degree_pred_kernel<<<NUM_BLOCKS, THREADS>>>(x, r_zeros, r_const,
                                                weights_t, weights_r, out);
}

// round 9
// speedup vs baseline: 1.0669x; 1.0669x over previous
#include <cuda_runtime.h>

// DegreePrediction: y[u] = sum_{s,t,v} (x*W_t)[s,t] * (W_r*r_zeros + r_const)[s,t,u,v]
// N = 80. Three 80^4 fp32 tensors (491.5 MB) streamed once.
//
// R9: persistent blocks. grid = 592 = 148 SMs x 4 blocks (exactly one wave).
// Each block grid-strides over 10-11 slices with the explicit prefetch
// pipeline carried ACROSS slice boundaries, and runs the (cheap) epilogue
// exactly once. R8 showed epilogue count is a first-order cost (3200 epilogues
// cost ~6us vs 1600); this cuts it to 592 and removes wave transitions.
//
// Layout: slice (s,t) = 1600 contiguous float4; u-row = 20 float4; thread tid,
// iter j reads float4 tid+320*j -> u = tid/20 + 16*j (constant per thread,j).

#define NN 80
#define SLICE_FLOATS (NN * NN)      // 6400
#define SLICE_F4 (SLICE_FLOATS / 4) // 1600
#define THREADS 320
#define J_ITERS 5
#define TOTAL_SLICES (NN * NN)      // 6400
#define GRID 592                    // 148 SMs * 4 blocks, single wave

__device__ float    g_scratch[NN];   // zero at load; kernel keeps it net-zero
__device__ unsigned g_count;         // ditto

__device__ __forceinline__ unsigned atom_inc_acq_rel(unsigned* p) {
    unsigned old;
    asm volatile("atom.add.acq_rel.gpu.global.u32 %0, [%1], 1;"
                 : "=r"(old) : "l"(p) : "memory");
    return old;
}

__global__ __launch_bounds__(THREADS, 4)
void degree_pred_kernel(const float* __restrict__ x,
                        const float* __restrict__ r_zeros,
                        const float* __restrict__ r_const,
                        const float* __restrict__ weights_t,
                        const float* __restrict__ weights_r,
                        float* __restrict__ out)
{
    __shared__ float y_part[J_ITERS][THREADS];
    __shared__ bool is_last;
    const int tid = threadIdx.x;
    const int bid = blockIdx.x;

    const float4* __restrict__ rz0 = reinterpret_cast<const float4*>(r_zeros);
    const float4* __restrict__ rc0 = reinterpret_cast<const float4*>(r_const);
    const float4* __restrict__ wr0 = reinterpret_cast<const float4*>(weights_r);

    const int nslice = (TOTAL_SLICES - 1 - bid) / GRID + 1;   // 10 or 11

    float acc[J_ITERS];
#pragma unroll
    for (int j = 0; j < J_ITERS; j++) acc[j] = 0.0f;

    // ---- prologue: prefetch (slice = bid, j = 0) ----
    int   slice  = bid;
    size_t qbase = (size_t)slice * SLICE_F4;   // float4 index of slice start
    float a_cur  = __ldg(&x[slice]) * __ldg(&weights_t[slice]);

    float4 z0 = __ldcs(&rz0[qbase + tid]);
    float4 c0 = __ldcs(&rc0[qbase + tid]);
    float4 w0 = __ldcs(&wr0[qbase + tid]);

    for (int s_idx = 0; s_idx < nslice; s_idx++) {
        const bool has_next = (s_idx + 1 < nslice);
        const int  nslice_id = has_next ? (slice + GRID) : slice;  // clamped, no OOB
        const size_t nqbase = (size_t)nslice_id * SLICE_F4;
        const float a_next  = __ldg(&x[nslice_id]) * __ldg(&weights_t[nslice_id]);

#pragma unroll
        for (int j = 0; j < J_ITERS; j++) {
            // prefetch next iteration (next j, or j=0 of next slice)
            float4 z1, c1, w1;
            if (j < J_ITERS - 1) {
                const size_t p = qbase + tid + THREADS * (j + 1);
                z1 = __ldcs(&rz0[p]);
                c1 = __ldcs(&rc0[p]);
                w1 = __ldcs(&wr0[p]);
            } else if (has_next) {
                const size_t p = nqbase + tid;
                z1 = __ldcs(&rz0[p]);
                c1 = __ldcs(&rc0[p]);
                w1 = __ldcs(&wr0[p]);
            }

            float t = (c0.x + c0.y) + (c0.z + c0.w);
            t = fmaf(w0.x, z0.x, t);
            t = fmaf(w0.y, z0.y, t);
            t = fmaf(w0.z, z0.z, t);
            t = fmaf(w0.w, z0.w, t);
            acc[j] = fmaf(a_cur, t, acc[j]);

            z0 = z1; c0 = c1; w0 = w1;
        }

        slice = nslice_id;
        qbase = nqbase;
        a_cur = a_next;
    }

    // ---- epilogue (once per block): STS transpose + 80-thread gather ----
#pragma unroll
    for (int j = 0; j < J_ITERS; j++)
        y_part[j][tid] = acc[j];
    __syncthreads();

    if (tid < NN) {
        const int u = tid;
        const int j = u >> 4;            // u / 16
        const int b = (u & 15) * 20;     // first of 20 contributing threads
        float s = 0.0f;
#pragma unroll
        for (int d = 0; d < 20; d++)
            s += y_part[j][b + d];
        atomicAdd(&g_scratch[u], s);     // relaxed; published by acq_rel below
    }
    __syncthreads();

    // ---- last-block finalize (no full membar, no L1 flush) ----
    if (tid == 0)
        is_last = (atom_inc_acq_rel(&g_count) == (unsigned)(GRID - 1));
    __syncthreads();

    if (is_last) {
        if (tid < NN) {
            float v = __ldcg(&g_scratch[tid]);   // L2 read, coherent w/ atomics
            out[tid] = v;
            g_scratch[tid] = 0.0f;               // restore initial state
        }
        __syncthreads();
        if (tid == 0) g_count = 0u;              // restore initial state
    }
}

extern "C" void kernel_launch(void* const* d_in, const int* in_sizes, int n_in,
                              void* d_out, int out_size)
{
    const float* x         = (const float*)d_in[0];
    const float* r_zeros   = (const float*)d_in[1];
    const float* r_const   = (const float*)d_in[2];
    const float* weights_t = (const float*)d_in[3];
    const float* weights_r = (const float*)d_in[4];
    float* out = (float*)d_out;

    degree_pred_kernel<<<GRID, THREADS>>>(x, r_zeros, r_const,
                                          weights_t, weights_r, out);
}